// round 6
// baseline (speedup 1.0000x reference)
#include <cuda_runtime.h>
#include <cstdint>
#include <math.h>

// Problem dimensions
#define BB 256
#define TT 64
#define EE 1024
#define AA 6
#define DD 256
#define SS 32
#define CC 32
#define HH 256
#define SDIM 1024
#define OUTW 4352   // 4*SD + D per (b,t)

#define NGUM (2 * TT * BB * SS * CC)   // 4194304

// ---------------- device scratch (no allocation allowed) ----------------
__device__ float g_gumbel[NGUM];                    // 16 MB
__device__ float g_deter[BB * DD];
__device__ float g_stoch[BB * SDIM];
__device__ float g_xpart[4 * BB * HH];              // split-K partials of x (+bias in part 0)
__device__ float g_gi[BB * 768];
__device__ float g_gh[BB * 768];
__device__ float g_postpart[2 * BB * SDIM];         // split-K partials of post_logits (no bias)

// ---------------- generic fp32 tiled GEMM core ----------------
// C[m, n] = sum_k A(m,k) * B[k, n_off+n]  (+ bias), A supplied by functor.
template<int BM, int BN, int BK, int NTHR, class AL>
__device__ __forceinline__ void gemm_core(
    AL aload,
    const float* __restrict__ Bm, int ldb,
    int m_off, int n_off, int k_begin, int k_end,
    float* __restrict__ C, long ldc,
    const float* __restrict__ bias)
{
    __shared__ __align__(16) float As[BK][BM];
    __shared__ __align__(16) float Bs[BK][BN];
    const int tid = threadIdx.x;
    constexpr int TM = 4, TN = 4;
    constexpr int NCOL = BN / TN;
    const int tx = tid % NCOL;
    const int ty = tid / NCOL;

    float acc[TM][TN];
#pragma unroll
    for (int i = 0; i < TM; i++)
#pragma unroll
        for (int j = 0; j < TN; j++) acc[i][j] = 0.f;

    for (int k0 = k_begin; k0 < k_end; k0 += BK) {
#pragma unroll
        for (int i = tid; i < BM * BK; i += NTHR) {
            int m = i / BK, kk = i % BK;
            int k = k0 + kk;
            As[kk][m] = (k < k_end) ? aload(m_off + m, k) : 0.f;
        }
#pragma unroll
        for (int i = tid; i < BK * BN; i += NTHR) {
            int kk = i / BN, n = i % BN;
            int k = k0 + kk;
            Bs[kk][n] = (k < k_end) ? Bm[(long)k * ldb + n_off + n] : 0.f;
        }
        __syncthreads();
#pragma unroll
        for (int kk = 0; kk < BK; kk++) {
            float4 av = *reinterpret_cast<const float4*>(&As[kk][ty * TM]);
            float4 bv = *reinterpret_cast<const float4*>(&Bs[kk][tx * TN]);
            float am[4] = {av.x, av.y, av.z, av.w};
            float bn[4] = {bv.x, bv.y, bv.z, bv.w};
#pragma unroll
            for (int i = 0; i < TM; i++)
#pragma unroll
                for (int j = 0; j < TN; j++) acc[i][j] += am[i] * bn[j];
        }
        __syncthreads();
    }
#pragma unroll
    for (int i = 0; i < TM; i++) {
        int m = m_off + ty * TM + i;
#pragma unroll
        for (int j = 0; j < TN; j++) {
            int n = n_off + tx * TN + j;
            float v = acc[i][j];
            if (bias) v += bias[n];
            C[(long)m * ldc + n] = v;
        }
    }
}

// ---------------- init ----------------
__global__ void k_init() {
    int i = blockIdx.x * blockDim.x + threadIdx.x;
    if (i < BB * DD)   g_deter[i] = 0.f;
    if (i < BB * SDIM) g_stoch[i] = 0.f;
}

// ---------------- JAX threefry2x32 gumbel noise (PARTITIONABLE scheme) ----
// Modern JAX (jax_threefry_partitionable=True, the default) generates 32-bit
// random words per-element: counter = (hi=0, lo=flat_index), key=(0,42),
// output word = out0 ^ out1.
__device__ __forceinline__ uint32_t rotl32(uint32_t v, int r) {
    return (v << r) | (v >> (32 - r));
}

// Matches jax.random.gumbel: -log(-log(uniform(tiny, 1))).
// Double-precision log => correctly-rounded fp32, immune to fast-math flags.
__device__ __forceinline__ float bits_to_gumbel(uint32_t b) {
    float u = __uint_as_float((b >> 9) | 0x3f800000u) - 1.0f;
    const float tinyv = 1.17549435e-38f;
    // XLA: max(tiny, f*(1-tiny)+tiny); (1-tiny) rounds to 1.0f, f+tiny rounds
    // to f for every nonzero representable f here, so this is exactly:
    u = fmaxf(u, tinyv);
    double inner = -log((double)u);
    float innerf = (float)inner;               // XLA keeps inner log in f32
    double outer = -log((double)innerf);
    return (float)outer;
}

__global__ void k_gumbel() {
    unsigned i = blockIdx.x * blockDim.x + threadIdx.x;
    if (i >= (unsigned)NGUM) return;
    uint32_t x0 = 0u, x1 = i;                  // counter (hi, lo) = (0, i)
    const uint32_t ks0 = 0u, ks1 = 42u, ks2 = 0x1BD11BDAu ^ 0u ^ 42u;
    x0 += ks0; x1 += ks1;
#define TF_R4(a, b, c, d)                                   \
    x0 += x1; x1 = rotl32(x1, a); x1 ^= x0;                 \
    x0 += x1; x1 = rotl32(x1, b); x1 ^= x0;                 \
    x0 += x1; x1 = rotl32(x1, c); x1 ^= x0;                 \
    x0 += x1; x1 = rotl32(x1, d); x1 ^= x0;
    TF_R4(13, 15, 26, 6);  x0 += ks1; x1 += ks2 + 1u;
    TF_R4(17, 29, 16, 24); x0 += ks2; x1 += ks0 + 2u;
    TF_R4(13, 15, 26, 6);  x0 += ks0; x1 += ks1 + 3u;
    TF_R4(17, 29, 16, 24); x0 += ks1; x1 += ks2 + 4u;
    TF_R4(13, 15, 26, 6);  x0 += ks2; x1 += ks0 + 5u;
#undef TF_R4
    g_gumbel[i] = bits_to_gumbel(x0 ^ x1);     // partitionable 32-bit combine
}

// ---------------- step kernels ----------------

// x = [stoch*mask | action_t] @ W_img_in (+b in split 0), split-K=4 partials
struct XLoad {
    const float* action; const float* isf; int t;
    __device__ float operator()(int m, int k) const {
        if (k < SDIM) return g_stoch[m * SDIM + k] * (1.0f - isf[m * TT + t]);
        return action[((long)m * TT + t) * AA + (k - SDIM)];
    }
};
__global__ void __launch_bounds__(256)
k_gemm_x(const float* __restrict__ action, const float* __restrict__ isf,
         const float* __restrict__ W, const float* __restrict__ bias, int t) {
    int z = blockIdx.z;
    int kb = z * 272;
    int ke = min(1030, kb + 272);
    gemm_core<64, 64, 16, 256>(XLoad{action, isf, t}, W, HH,
                               blockIdx.y * 64, blockIdx.x * 64, kb, ke,
                               g_xpart + z * (BB * HH), HH, (z == 0) ? bias : nullptr);
}

// gi = x @ W_ih + b_ih ; gh = (deter*mask) @ W_hh + b_hh   (grid.z selects)
struct GiLoad {
    __device__ float operator()(int m, int k) const {
        int i = m * HH + k;
        return g_xpart[i] + g_xpart[BB * HH + i] + g_xpart[2 * BB * HH + i] + g_xpart[3 * BB * HH + i];
    }
};
struct GhLoad {
    const float* isf; int t;
    __device__ float operator()(int m, int k) const {
        return g_deter[m * DD + k] * (1.0f - isf[m * TT + t]);
    }
};
__global__ void __launch_bounds__(256)
k_gemm_gates(const float* __restrict__ Wih, const float* __restrict__ bih,
             const float* __restrict__ Whh, const float* __restrict__ bhh,
             const float* __restrict__ isf, int t) {
    if (blockIdx.z == 0)
        gemm_core<64, 64, 16, 256>(GiLoad{}, Wih, 768,
                                   blockIdx.y * 64, blockIdx.x * 64, 0, DD, g_gi, 768, bih);
    else
        gemm_core<64, 64, 16, 256>(GhLoad{isf, t}, Whh, 768,
                                   blockIdx.y * 64, blockIdx.x * 64, 0, DD, g_gh, 768, bhh);
}

// GRU combine -> new deter; also writes deter slice of the output.
// Double-precision exp/tanh: correctly-rounded, fast-math-immune.
__device__ __forceinline__ float sigm_precise(float x) {
    return (float)(1.0 / (1.0 + exp((double)(-x))));
}
__device__ __forceinline__ float tanh_precise(float x) {
    return (float)tanh((double)x);
}

__global__ void k_gru(const float* __restrict__ isf, float* __restrict__ out, int t) {
    int i = blockIdx.x * blockDim.x + threadIdx.x;   // 65536 threads
    int b = i >> 8, d = i & 255;
    float ir = g_gi[b * 768 + d], iz = g_gi[b * 768 + 256 + d], in_ = g_gi[b * 768 + 512 + d];
    float hr = g_gh[b * 768 + d], hz = g_gh[b * 768 + 256 + d], hn = g_gh[b * 768 + 512 + d];
    float r = sigm_precise(ir + hr);
    float z = sigm_precise(iz + hz);
    float n = tanh_precise(in_ + r * hn);
    float h = g_deter[i] * (1.0f - isf[b * TT + t]);
    float nd = (1.0f - z) * n + z * h;
    g_deter[i] = nd;
    out[((long)b * TT + t) * OUTW + 2048 + d] = nd;
}

// z=0: prior_logits = deter @ W_img_out + b  (straight into d_out)
// z=1,2: post_logits split-K halves of [deter|emb_t] @ W_obs_out (no bias; partials)
struct DetLoad {
    __device__ float operator()(int m, int k) const { return g_deter[m * DD + k]; }
};
struct PostLoad {
    const float* embed; int t;
    __device__ float operator()(int m, int k) const {
        if (k < DD) return g_deter[m * DD + k];
        return embed[((long)m * TT + t) * EE + (k - DD)];
    }
};
__global__ void __launch_bounds__(256)
k_gemm_out(const float* __restrict__ embed,
           const float* __restrict__ Wio, const float* __restrict__ bio,
           const float* __restrict__ Woo,
           float* __restrict__ out, int t) {
    int z = blockIdx.z;
    if (z == 0) {
        gemm_core<64, 64, 16, 256>(DetLoad{}, Wio, SDIM,
                                   blockIdx.y * 64, blockIdx.x * 64, 0, DD,
                                   out + (long)t * OUTW + 2304, (long)TT * OUTW, bio);
    } else {
        int kb = (z == 1) ? 0 : 640;
        int ke = (z == 1) ? 640 : 1280;
        gemm_core<64, 64, 16, 256>(PostLoad{embed, t}, Woo, SDIM,
                                   blockIdx.y * 64, blockIdx.x * 64, kb, ke,
                                   g_postpart + (z - 1) * (BB * SDIM), SDIM, nullptr);
    }
}

// sampling: warp per (draw, b, s); assembles post logits (partials+bias), writes
// them to out, argmax(logit + gumbel) -> one-hot, post one-hot also -> g_stoch.
// Tie-break: lowest index (matches jnp.argmax first-max semantics).
__global__ void k_sample(const float* __restrict__ boo, float* __restrict__ out, int t) {
    int w = (blockIdx.x * blockDim.x + threadIdx.x) >> 5;
    int lane = threadIdx.x & 31;
    int draw = w / (BB * SS);
    int r = w % (BB * SS);
    int b = r / SS, s = r % SS;
    long obase = ((long)b * TT + t) * OUTW;
    int col = s * 32 + lane;
    float lv;
    if (draw == 0) {
        lv = out[obase + 2304 + col];
    } else {
        lv = g_postpart[b * SDIM + col] + g_postpart[BB * SDIM + b * SDIM + col] + boo[col];
        out[obase + col] = lv;
    }
    float g = g_gumbel[((((long)draw * TT + t) * BB + b) * SS + s) * CC + lane];
    float v = lv + g;
    int idx = lane;
#pragma unroll
    for (int off = 16; off > 0; off >>= 1) {
        float v2 = __shfl_xor_sync(0xffffffffu, v, off);
        int i2 = __shfl_xor_sync(0xffffffffu, idx, off);
        if (v2 > v || (v2 == v && i2 < idx)) { v = v2; idx = i2; }
    }
    float oh = (lane == idx) ? 1.0f : 0.0f;
    out[obase + (draw ? 1024 : 3328) + col] = oh;
    if (draw) g_stoch[b * SDIM + col] = oh;
}

// ---------------- launch ----------------
extern "C" void kernel_launch(void* const* d_in, const int* in_sizes, int n_in,
                              void* d_out, int out_size) {
    (void)in_sizes; (void)n_in; (void)out_size;
    const float* embed     = (const float*)d_in[0];
    const float* action    = (const float*)d_in[1];
    const float* isf       = (const float*)d_in[2];
    const float* W_img_in  = (const float*)d_in[3];
    const float* b_img_in  = (const float*)d_in[4];
    const float* W_ih      = (const float*)d_in[5];
    const float* b_ih      = (const float*)d_in[6];
    const float* W_hh      = (const float*)d_in[7];
    const float* b_hh      = (const float*)d_in[8];
    const float* W_img_out = (const float*)d_in[9];
    const float* b_img_out = (const float*)d_in[10];
    const float* W_obs_out = (const float*)d_in[11];
    const float* b_obs_out = (const float*)d_in[12];
    float* out = (float*)d_out;

    k_gumbel<<<NGUM / 256, 256>>>();
    k_init<<<1024, 256>>>();
    for (int t = 0; t < TT; t++) {
        k_gemm_x<<<dim3(4, 4, 4), 256>>>(action, isf, W_img_in, b_img_in, t);
        k_gemm_gates<<<dim3(12, 4, 2), 256>>>(W_ih, b_ih, W_hh, b_hh, isf, t);
        k_gru<<<256, 256>>>(isf, out, t);
        k_gemm_out<<<dim3(16, 4, 3), 256>>>(embed, W_img_out, b_img_out, W_obs_out, out, t);
        k_sample<<<2048, 256>>>(b_obs_out, out, t);
    }
}

// round 7
// speedup vs baseline: 3.8395x; 3.8395x over previous
#include <cuda_runtime.h>
#include <cstdint>
#include <math.h>

// Problem dimensions
#define BB 256
#define TT 64
#define EE 1024
#define AA 6
#define DD 256
#define SS 32
#define CC 32
#define HH 256
#define SDIM 1024
#define OUTW 4352   // 4*SD + D per (b,t)

#define NGUM (2 * TT * BB * SS * CC)   // 4194304

// ---------------- device scratch (no allocation allowed) ----------------
__device__ float g_gumbel[NGUM];                    // 16 MB
__device__ float g_deter[BB * DD];
__device__ float g_x[BB * HH];                      // GRU input x(t), fed forward
__device__ float g_gi[BB * 768];
__device__ float g_gh[BB * 768];
__device__ float g_dpart[BB * SDIM];                // deter part of post logits
__device__ float g_epart[(long)BB * TT * SDIM];     // embed part of post logits (64 MB)

// ---------------- double-buffered fp32 tiled GEMM core ------------------
// C[m,n] = sum_{k in [k0, k0+kcnt)} A(m,k)*B[k, n_off+n] (+bias).
// kcnt must be a multiple of BK. Per-thread accumulation is pure K-order
// (identical to the R6 single-buffer core -> bit-identical results).
template<int BM, int BN, int BK, int NTHR, class AL>
__device__ __forceinline__ void gemm_db(
    AL aload, const float* __restrict__ Bm, int ldb,
    int m_off, int n_off, int k0, int kcnt,
    float* __restrict__ C, long ldc, const float* __restrict__ bias)
{
    constexpr int APAD = 4;
    __shared__ __align__(16) float As[2][BK][BM + APAD];
    __shared__ __align__(16) float Bs[2][BK][BN];
    const int tid = threadIdx.x;
    constexpr int TM = 4, TN = 4;
    constexpr int NCOL = BN / TN;
    const int tx = tid % NCOL;
    const int ty = tid / NCOL;
    constexpr int ALD = BM * BK / NTHR;   // elems/thread for A
    constexpr int BLD = BN * BK / NTHR;
    const int amk = tid % BK;             // A: fixed kk
    const int am0 = tid / BK;             // A: base m, step NTHR/BK
    const int bn  = tid % BN;             // B: fixed n
    const int bk0 = tid / BN;             // B: base kk, step NTHR/BN

    float rA[ALD], rB[BLD];
    float acc[TM][TN];
#pragma unroll
    for (int i = 0; i < TM; i++)
#pragma unroll
        for (int j = 0; j < TN; j++) acc[i][j] = 0.f;

    const int NT = kcnt / BK;

    // preload tile 0
#pragma unroll
    for (int j = 0; j < ALD; j++)
        rA[j] = aload(m_off + am0 + j * (NTHR / BK), k0 + amk);
#pragma unroll
    for (int j = 0; j < BLD; j++)
        rB[j] = Bm[(long)(k0 + bk0 + j * (NTHR / BN)) * ldb + n_off + bn];
#pragma unroll
    for (int j = 0; j < ALD; j++) As[0][amk][am0 + j * (NTHR / BK)] = rA[j];
#pragma unroll
    for (int j = 0; j < BLD; j++) Bs[0][bk0 + j * (NTHR / BN)][bn] = rB[j];
    __syncthreads();

    for (int kt = 0; kt < NT; kt++) {
        int cur = kt & 1;
        if (kt + 1 < NT) {
            int kb = k0 + (kt + 1) * BK;
#pragma unroll
            for (int j = 0; j < ALD; j++)
                rA[j] = aload(m_off + am0 + j * (NTHR / BK), kb + amk);
#pragma unroll
            for (int j = 0; j < BLD; j++)
                rB[j] = Bm[(long)(kb + bk0 + j * (NTHR / BN)) * ldb + n_off + bn];
        }
#pragma unroll
        for (int kk = 0; kk < BK; kk++) {
            float4 av = *reinterpret_cast<const float4*>(&As[cur][kk][ty * TM]);
            float4 bv = *reinterpret_cast<const float4*>(&Bs[cur][kk][tx * TN]);
            float am[4] = {av.x, av.y, av.z, av.w};
            float bn_[4] = {bv.x, bv.y, bv.z, bv.w};
#pragma unroll
            for (int i = 0; i < TM; i++)
#pragma unroll
                for (int j = 0; j < TN; j++) acc[i][j] += am[i] * bn_[j];
        }
        if (kt + 1 < NT) {
            int nb = cur ^ 1;
#pragma unroll
            for (int j = 0; j < ALD; j++) As[nb][amk][am0 + j * (NTHR / BK)] = rA[j];
#pragma unroll
            for (int j = 0; j < BLD; j++) Bs[nb][bk0 + j * (NTHR / BN)][bn] = rB[j];
            __syncthreads();
        }
    }
#pragma unroll
    for (int i = 0; i < TM; i++) {
        int m = m_off + ty * TM + i;
#pragma unroll
        for (int j = 0; j < TN; j++) {
            int n = n_off + tx * TN + j;
            float v = acc[i][j];
            if (bias) v += bias[n];
            C[(long)m * ldc + n] = v;
        }
    }
}

// ---------------- upfront: embed part of post logits --------------------
// g_epart[M, n] = sum_e embed[M, e] * W_obs_out[256 + e][n],  M = b*T + t.
__global__ void __launch_bounds__(256, 2)
k_embpart(const float* __restrict__ E, const float* __restrict__ Woo) {
    __shared__ __align__(16) float As[2][8][128 + 4];
    __shared__ __align__(16) float Bs[2][8][128];
    const int tid = threadIdx.x;
    const int N0 = blockIdx.x * 128, M0 = blockIdx.y * 128;
    const int am = tid >> 1, aq = tid & 1;    // A: row am, float4 at k+aq*4
    const int bk = tid >> 5, bn4 = tid & 31;  // B: row k+bk, float4 at N0+bn4*4
    const int tx = tid % 16, ty = tid / 16;

    float4 ra, rb;
    float acc[8][8];
#pragma unroll
    for (int i = 0; i < 8; i++)
#pragma unroll
        for (int j = 0; j < 8; j++) acc[i][j] = 0.f;

    const float* Ap = E + (long)(M0 + am) * EE + aq * 4;
    const float* Bp = Woo + (long)(DD + bk) * SDIM + N0 + bn4 * 4;

    ra = *reinterpret_cast<const float4*>(Ap);
    rb = *reinterpret_cast<const float4*>(Bp);
    As[0][aq * 4 + 0][am] = ra.x; As[0][aq * 4 + 1][am] = ra.y;
    As[0][aq * 4 + 2][am] = ra.z; As[0][aq * 4 + 3][am] = ra.w;
    *reinterpret_cast<float4*>(&Bs[0][bk][bn4 * 4]) = rb;
    __syncthreads();

    for (int kt = 0; kt < 128; kt++) {
        int cur = kt & 1;
        if (kt + 1 < 128) {
            int kb = (kt + 1) * 8;
            ra = *reinterpret_cast<const float4*>(Ap + kb);
            rb = *reinterpret_cast<const float4*>(Bp + (long)kb * SDIM);
        }
#pragma unroll
        for (int kk = 0; kk < 8; kk++) {
            float4 a0 = *reinterpret_cast<const float4*>(&As[cur][kk][ty * 8]);
            float4 a1 = *reinterpret_cast<const float4*>(&As[cur][kk][ty * 8 + 4]);
            float4 b0 = *reinterpret_cast<const float4*>(&Bs[cur][kk][tx * 8]);
            float4 b1 = *reinterpret_cast<const float4*>(&Bs[cur][kk][tx * 8 + 4]);
            float a[8] = {a0.x, a0.y, a0.z, a0.w, a1.x, a1.y, a1.z, a1.w};
            float b[8] = {b0.x, b0.y, b0.z, b0.w, b1.x, b1.y, b1.z, b1.w};
#pragma unroll
            for (int i = 0; i < 8; i++)
#pragma unroll
                for (int j = 0; j < 8; j++) acc[i][j] += a[i] * b[j];
        }
        if (kt + 1 < 128) {
            int nb = cur ^ 1;
            As[nb][aq * 4 + 0][am] = ra.x; As[nb][aq * 4 + 1][am] = ra.y;
            As[nb][aq * 4 + 2][am] = ra.z; As[nb][aq * 4 + 3][am] = ra.w;
            *reinterpret_cast<float4*>(&Bs[nb][bk][bn4 * 4]) = rb;
            __syncthreads();
        }
    }
#pragma unroll
    for (int i = 0; i < 8; i++) {
        long row = (long)(M0 + ty * 8 + i) * SDIM + N0 + tx * 8;
        *reinterpret_cast<float4*>(&g_epart[row])     = make_float4(acc[i][0], acc[i][1], acc[i][2], acc[i][3]);
        *reinterpret_cast<float4*>(&g_epart[row + 4]) = make_float4(acc[i][4], acc[i][5], acc[i][6], acc[i][7]);
    }
}

// ---------------- init ----------------
__global__ void k_init() {
    int i = blockIdx.x * blockDim.x + threadIdx.x;
    g_deter[i] = 0.f;
}

// x(0): stoch=0 -> chunks c0..c2 = +0, so x = b_img_in + (action-term chain).
__global__ void k_x0(const float* __restrict__ action, const float* __restrict__ W1,
                     const float* __restrict__ b1) {
    int b = blockIdx.x, col = threadIdx.x;
    float c3 = 0.f;
#pragma unroll
    for (int a = 0; a < AA; a++)
        c3 = fmaf(action[(long)b * TT * AA + a], W1[(SDIM + a) * HH + col], c3);
    g_x[b * HH + col] = b1[col] + c3;
}

// ---------------- JAX threefry2x32 gumbel (partitionable scheme) --------
__device__ __forceinline__ uint32_t rotl32(uint32_t v, int r) {
    return (v << r) | (v >> (32 - r));
}
__device__ __forceinline__ float bits_to_gumbel(uint32_t b) {
    float u = __uint_as_float((b >> 9) | 0x3f800000u) - 1.0f;
    const float tinyv = 1.17549435e-38f;
    u = fmaxf(u, tinyv);
    double inner = -log((double)u);
    float innerf = (float)inner;
    double outer = -log((double)innerf);
    return (float)outer;
}
__global__ void k_gumbel() {
    unsigned i = blockIdx.x * blockDim.x + threadIdx.x;
    if (i >= (unsigned)NGUM) return;
    uint32_t x0 = 0u, x1 = i;
    const uint32_t ks0 = 0u, ks1 = 42u, ks2 = 0x1BD11BDAu ^ 0u ^ 42u;
    x0 += ks0; x1 += ks1;
#define TF_R4(a, b, c, d)                                   \
    x0 += x1; x1 = rotl32(x1, a); x1 ^= x0;                 \
    x0 += x1; x1 = rotl32(x1, b); x1 ^= x0;                 \
    x0 += x1; x1 = rotl32(x1, c); x1 ^= x0;                 \
    x0 += x1; x1 = rotl32(x1, d); x1 ^= x0;
    TF_R4(13, 15, 26, 6);  x0 += ks1; x1 += ks2 + 1u;
    TF_R4(17, 29, 16, 24); x0 += ks2; x1 += ks0 + 2u;
    TF_R4(13, 15, 26, 6);  x0 += ks0; x1 += ks1 + 3u;
    TF_R4(17, 29, 16, 24); x0 += ks1; x1 += ks2 + 4u;
    TF_R4(13, 15, 26, 6);  x0 += ks2; x1 += ks0 + 5u;
#undef TF_R4
    g_gumbel[i] = bits_to_gumbel(x0 ^ x1);
}

// ---------------- per-step kernels ----------------

struct GiL {
    __device__ float operator()(int m, int k) const { return g_x[m * HH + k]; }
};
struct GhL {
    const float* isf; int t;
    __device__ float operator()(int m, int k) const {
        return g_deter[m * DD + k] * (1.0f - isf[m * TT + t]);
    }
};
__global__ void __launch_bounds__(256)
k_gates(const float* __restrict__ Wih, const float* __restrict__ bih,
        const float* __restrict__ Whh, const float* __restrict__ bhh,
        const float* __restrict__ isf, int t) {
    if (blockIdx.z == 0)
        gemm_db<64, 64, 16, 256>(GiL{}, Wih, 768,
                                 blockIdx.y * 64, blockIdx.x * 64, 0, DD, g_gi, 768, bih);
    else
        gemm_db<64, 64, 16, 256>(GhL{isf, t}, Whh, 768,
                                 blockIdx.y * 64, blockIdx.x * 64, 0, DD, g_gh, 768, bhh);
}

__device__ __forceinline__ float sigm_precise(float x) {
    return (float)(1.0 / (1.0 + exp((double)(-x))));
}
__device__ __forceinline__ float tanh_precise(float x) {
    return (float)tanh((double)x);
}
__global__ void k_gru(const float* __restrict__ isf, float* __restrict__ out, int t) {
    int i = blockIdx.x * blockDim.x + threadIdx.x;
    int b = i >> 8, d = i & 255;
    float ir = g_gi[b * 768 + d], iz = g_gi[b * 768 + 256 + d], in_ = g_gi[b * 768 + 512 + d];
    float hr = g_gh[b * 768 + d], hz = g_gh[b * 768 + 256 + d], hn = g_gh[b * 768 + 512 + d];
    float r = sigm_precise(ir + hr);
    float z = sigm_precise(iz + hz);
    float n = tanh_precise(in_ + r * hn);
    float h = g_deter[i] * (1.0f - isf[b * TT + t]);
    float nd = (1.0f - z) * n + z * h;
    g_deter[i] = nd;
    out[((long)b * TT + t) * OUTW + 2048 + d] = nd;
}

struct DetL {
    __device__ float operator()(int m, int k) const { return g_deter[m * DD + k]; }
};
__global__ void __launch_bounds__(256)
k_out(const float* __restrict__ Wio, const float* __restrict__ bio,
      const float* __restrict__ Woo, float* __restrict__ out, int t) {
    if (blockIdx.z == 0)
        gemm_db<64, 64, 16, 256>(DetL{}, Wio, SDIM,
                                 blockIdx.y * 64, blockIdx.x * 64, 0, DD,
                                 out + (long)t * OUTW + 2304, (long)TT * OUTW, bio);
    else
        gemm_db<64, 64, 16, 256>(DetL{}, Woo, SDIM,
                                 blockIdx.y * 64, blockIdx.x * 64, 0, DD,
                                 g_dpart, SDIM, nullptr);
}

// sampling + feedback. blockIdx.y: 0=prior draw, 1=post draw.
// post block also computes x(t+1), bit-exactly emulating the R6 split-K-4
// grouping of [stoch|action] @ W_img_in (chunk bounds 272/544/816).
__global__ void k_sample(const float* __restrict__ isf, const float* __restrict__ action,
                         const float* __restrict__ W1, const float* __restrict__ b1,
                         const float* __restrict__ boo, float* __restrict__ out, int t) {
    int b = blockIdx.x;
    int draw = blockIdx.y;
    int tid = threadIdx.x, lane = tid & 31, w = tid >> 5;
    __shared__ int sidx[SS];
    long obase = ((long)b * TT + t) * OUTW;

#pragma unroll
    for (int q = 0; q < 4; q++) {
        int g = w * 4 + q;
        int col = g * 32 + lane;
        float lv;
        if (draw == 0) {
            lv = out[obase + 2304 + col];
        } else {
            lv = (g_dpart[b * SDIM + col] + g_epart[((long)b * TT + t) * SDIM + col]) + boo[col];
            out[obase + col] = lv;
        }
        float gum = g_gumbel[(((long)draw * TT + t) * BB + b) * SDIM + col];
        float v = lv + gum;
        int idx = lane;
#pragma unroll
        for (int off = 16; off > 0; off >>= 1) {
            float v2 = __shfl_xor_sync(0xffffffffu, v, off);
            int i2 = __shfl_xor_sync(0xffffffffu, idx, off);
            if (v2 > v || (v2 == v && i2 < idx)) { v = v2; idx = i2; }
        }
        float oh = (lane == idx) ? 1.0f : 0.0f;
        out[obase + (draw ? 1024 : 3328) + col] = oh;
        if (draw && lane == 0) sidx[g] = idx;
    }

    if (draw == 1 && t + 1 < TT) {
        __syncthreads();
        int col = tid;
        float mask = 1.0f - isf[b * TT + (t + 1)];
        float c0 = 0.f, c1 = 0.f, c2 = 0.f, c3 = 0.f;
        int i8 = sidx[8], i25 = sidx[25];
#pragma unroll
        for (int s = 0; s < 8; s++)
            c0 = fmaf(mask, W1[(s * 32 + sidx[s]) * HH + col], c0);
        {
            float wv = W1[(8 * 32 + i8) * HH + col];
            if (i8 < 16) c0 = fmaf(mask, wv, c0); else c1 = fmaf(mask, wv, c1);
        }
#pragma unroll
        for (int s = 9; s < 17; s++)
            c1 = fmaf(mask, W1[(s * 32 + sidx[s]) * HH + col], c1);
#pragma unroll
        for (int s = 17; s < 25; s++)
            c2 = fmaf(mask, W1[(s * 32 + sidx[s]) * HH + col], c2);
        {
            float wv = W1[(25 * 32 + i25) * HH + col];
            if (i25 < 16) c2 = fmaf(mask, wv, c2); else c3 = fmaf(mask, wv, c3);
        }
#pragma unroll
        for (int s = 26; s < 32; s++)
            c3 = fmaf(mask, W1[(s * 32 + sidx[s]) * HH + col], c3);
#pragma unroll
        for (int a = 0; a < AA; a++)
            c3 = fmaf(action[((long)b * TT + (t + 1)) * AA + a], W1[(SDIM + a) * HH + col], c3);
        g_x[b * HH + col] = (((c0 + b1[col]) + c1) + c2) + c3;
    }
}

// ---------------- launch ----------------
extern "C" void kernel_launch(void* const* d_in, const int* in_sizes, int n_in,
                              void* d_out, int out_size) {
    (void)in_sizes; (void)n_in; (void)out_size;
    const float* embed     = (const float*)d_in[0];
    const float* action    = (const float*)d_in[1];
    const float* isf       = (const float*)d_in[2];
    const float* W_img_in  = (const float*)d_in[3];
    const float* b_img_in  = (const float*)d_in[4];
    const float* W_ih      = (const float*)d_in[5];
    const float* b_ih      = (const float*)d_in[6];
    const float* W_hh      = (const float*)d_in[7];
    const float* b_hh      = (const float*)d_in[8];
    const float* W_img_out = (const float*)d_in[9];
    const float* b_img_out = (const float*)d_in[10];
    const float* W_obs_out = (const float*)d_in[11];
    const float* b_obs_out = (const float*)d_in[12];
    float* out = (float*)d_out;

    k_embpart<<<dim3(8, 128), 256>>>(embed, W_obs_out);
    k_gumbel<<<NGUM / 256, 256>>>();
    k_init<<<256, 256>>>();
    k_x0<<<256, 256>>>(action, W_img_in, b_img_in);
    for (int t = 0; t < TT; t++) {
        k_gates<<<dim3(12, 4, 2), 256>>>(W_ih, b_ih, W_hh, b_hh, isf, t);
        k_gru<<<256, 256>>>(isf, out, t);
        k_out<<<dim3(16, 4, 2), 256>>>(W_img_out, b_img_out, W_obs_out, out, t);
        k_sample<<<dim3(256, 2), 256>>>(isf, action, W_img_in, b_img_in, b_obs_out, out, t);
    }
}